// round 6
// baseline (speedup 1.0000x reference)
#include <cuda_runtime.h>

#define TSTEPS  1024
#define BATCH   64
#define IN_DIM  256
#define HID_DIM 512
#define OUT_DIM 256
#define KDIM    768
#define NCTA    128
#define NTHR    768

// strides in floats
#define HSTRIDE_B (1025 * HID_DIM)   // Hout batch stride
#define RSTRIDE_B (1025 * OUT_DIM)   // Rout batch stride
#define XSTRIDE_B (TSTEPS * IN_DIM)  // X batch stride

// ---- global-barrier state (init + final reset only) ----
__device__ unsigned g_bar_count = 0;
__device__ volatile unsigned g_bar_gen = 0;

// ---- per-half monotonic epoch counters (separate L2 sectors) ----
__device__ unsigned g_cnt[2 * 64];

__device__ __forceinline__ void grid_barrier() {
    __syncthreads();
    if (threadIdx.x == 0) {
        __threadfence();
        unsigned g = g_bar_gen;
        if (atomicAdd(&g_bar_count, 1u) == NCTA - 1) {
            g_bar_count = 0;
            __threadfence();
            g_bar_gen = g + 1;
        } else {
            while (g_bar_gen == g) {}
            __threadfence();
        }
    }
    __syncthreads();
}

__device__ __forceinline__ void red_release_add1(unsigned* p) {
    asm volatile("red.release.gpu.add.u32 [%0], 1;" :: "l"(p) : "memory");
}
__device__ __forceinline__ unsigned ld_acquire_u32(const unsigned* p) {
    unsigned v;
    asm volatile("ld.acquire.gpu.u32 %0, [%1];" : "=r"(v) : "l"(p) : "memory");
    return v;
}

// Persistent RNN kernel, v6.
// 128 CTAs = 64 column-groups x 2 batch-halves. CTA = 768 threads = 24 warps.
//   column-group g owns h-cols [g*8,g*8+8), r-cols [g*4,g*4+4)
//   warp = (col-set cs in {0,1,2}) x (batch-oct boct, 4 rows)
//     cs 0/1: 4 h-cols (jh0+cs*4..)   cs 2: 4 r-cols (jr0..)
//   All warps: 384 FFMA/thread/iter (balanced).
// Addressing: one running pointer per stream; batch/k offsets are compile-time
// immediates folded into LDG/LDS offsets. One add per stream per iteration.
// Sync: per-half monotonic epoch counter (red.release + single-poller acquire,
// smem flag relay). x-dot for it+1 computed in the wait window.
__global__ void __launch_bounds__(NTHR, 1)
rnn_persistent_kernel(const float* __restrict__ X,    // [64][1024][256]
                      const float* __restrict__ H0,   // [64][512]
                      const float* __restrict__ R0,   // [64][256]
                      const float* __restrict__ Wih,  // [512][768]
                      const float* __restrict__ Bih,  // [512]
                      const float* __restrict__ Who,  // [256][768]
                      const float* __restrict__ Bho,  // [256]
                      float* __restrict__ Rout,       // [64][1025][256]
                      float* __restrict__ Hout)       // [64][1025][512]
{
    __shared__ float W1s[8][KDIM];   // W_ih rows jh0.. (k: 0..255 x | 256..767 h)
    __shared__ float W2s[4][KDIM];   // W_ho rows jr0.. (k: 0..511 h | 512..767 r)
    __shared__ float bih_s[8];
    __shared__ float bho_s[4];
    volatile __shared__ int bar_flag;

    const int tid  = threadIdx.x;
    const int cta  = blockIdx.x;
    const int grp  = cta >> 1;
    const int half = cta & 1;
    const int b0   = half * 32;
    const int jh0  = grp * 8;
    const int jr0  = grp * 4;
    const int wrp  = tid >> 5;
    const int lane = tid & 31;
    const int cs   = wrp >> 3;        // 0,1: h-col quads; 2: r-col quad
    const int boct = wrp & 7;
    const int bb0  = b0 + boct * 4;
    unsigned* cnt  = &g_cnt[half * 64];

    // ---- stationary weight slices -> smem ----
    for (int idx = tid; idx < 8 * KDIM; idx += NTHR) {
        int j = idx / KDIM, k = idx - j * KDIM;
        W1s[j][k] = Wih[(jh0 + j) * KDIM + k];
    }
    for (int idx = tid; idx < 4 * KDIM; idx += NTHR) {
        int j = idx / KDIM, k = idx - j * KDIM;
        W2s[j][k] = Who[(jr0 + j) * KDIM + k];
    }
    if (tid < 8) bih_s[tid] = Bih[jh0 + tid];
    if (tid < 4) bho_s[tid] = Bho[jr0 + tid];
    if (tid == 0) bar_flag = 0;

    // ---- t=0 states into output/exchange buffers ----
    for (int idx = tid; idx < 32 * 8; idx += NTHR) {
        int b = b0 + (idx >> 3), jj = idx & 7;
        Hout[(size_t)b * HSTRIDE_B + jh0 + jj] = H0[b * HID_DIM + jh0 + jj];
    }
    for (int idx = tid; idx < 32 * 4; idx += NTHR) {
        int b = b0 + (idx >> 2), jj = idx & 3;
        Rout[(size_t)b * RSTRIDE_B + jr0 + jj] = R0[b * OUT_DIM + jr0 + jj];
    }
    __syncthreads();

    // ---- running pointers (advance by constant each iteration) ----
    const float* pHr = Hout + (size_t)bb0 * HSTRIDE_B + 4 * lane;           // h[t=0]
    const float* pX  = X    + (size_t)bb0 * XSTRIDE_B + 4 * lane;           // x[t=0]
    const float* pRr = Rout + (size_t)bb0 * RSTRIDE_B + 4 * lane - OUT_DIM; // r[t=-1] (guarded)

    // per-lane write pointer + bias (lane < 16 only does stores)
    const int bl = lane >> 2, cc = lane & 3;
    float* pW;
    float bias;
    if (cs < 2) {
        pW   = Hout + (size_t)(bb0 + bl) * HSTRIDE_B + HID_DIM + jh0 + cs * 4 + cc; // t=1
        bias = bih_s[cs * 4 + cc];
    } else {
        pW   = Rout + (size_t)(bb0 + bl) * RSTRIDE_B + jr0 + cc;                    // t=0 (advances to t=it)
        bias = bho_s[cc];
    }

    // smem weight bases (lane-folded offsets become immediates)
    const float* Wh = (cs < 2) ? &W1s[cs * 4][256] : &W2s[0][0];  // h-dot weights
    const float* Wx = &W1s[cs * 4][0];                            // x-dot (cs<2)
    const float* Wr = &W2s[0][512];                               // r-dot (cs==2)

    // A[b*4+c]
    float A[16];
#pragma unroll
    for (int i = 0; i < 16; ++i) A[i] = 0.f;

    // ---- prologue: x-dot for it=0 (cs<2) ----
    if (cs < 2) {
#pragma unroll
        for (int i = 0; i < 2; ++i) {
            float4 w[4];
#pragma unroll
            for (int c = 0; c < 4; ++c) w[c] = *(const float4*)&Wx[c * KDIM + 4 * lane + 128 * i];
#pragma unroll
            for (int b = 0; b < 4; ++b) {
                const float4 a = *(const float4*)&pX[b * XSTRIDE_B + 128 * i];
#pragma unroll
                for (int c = 0; c < 4; ++c)
                    A[b * 4 + c] += a.x * w[c].x + a.y * w[c].y
                                  + a.z * w[c].z + a.w * w[c].w;
            }
        }
    }
    pX += IN_DIM;   // -> t=1

    grid_barrier();  // one-time: H0/R0 copies visible grid-wide

    for (int it = 0; it <= TSTEPS; ++it) {
        // ---- h[it] dot: cs<2 -> h-cols (W_ih k=256..), cs2 -> r-cols (W_ho k=0..511) ----
#pragma unroll
        for (int i = 0; i < 4; ++i) {
            float4 w[4];
#pragma unroll
            for (int c = 0; c < 4; ++c) w[c] = *(const float4*)&Wh[c * KDIM + 4 * lane + 128 * i];
#pragma unroll
            for (int b = 0; b < 4; ++b) {
                const float4 a = *(const float4*)&pHr[b * HSTRIDE_B + 128 * i];
#pragma unroll
                for (int c = 0; c < 4; ++c)
                    A[b * 4 + c] += a.x * w[c].x + a.y * w[c].y
                                  + a.z * w[c].z + a.w * w[c].w;
            }
        }

        // ---- r[it-1] dot (cs==2, it>=1) ----
        if (cs == 2 && it >= 1) {
#pragma unroll
            for (int i = 0; i < 2; ++i) {
                float4 w[4];
#pragma unroll
                for (int c = 0; c < 4; ++c) w[c] = *(const float4*)&Wr[c * KDIM + 4 * lane + 128 * i];
#pragma unroll
                for (int b = 0; b < 4; ++b) {
                    const float4 a = *(const float4*)&pRr[b * RSTRIDE_B + 128 * i];
#pragma unroll
                    for (int c = 0; c < 4; ++c)
                        A[b * 4 + c] += a.x * w[c].x + a.y * w[c].y
                                      + a.z * w[c].z + a.w * w[c].w;
                }
            }
        }

        // ---- transpose-butterfly reduction (31 shuffles), output L lands on lane L ----
#pragma unroll
        for (int off = 16; off >= 1; off >>= 1) {
#pragma unroll
            for (int i = 0; i < off && i < 16; ++i) {
                const int j = i + off;
                const float vj = (j < 16) ? A[j] : 0.f;
                const float send = (lane & off) ? A[i] : vj;
                const float recv = __shfl_xor_sync(0xffffffffu, send, off);
                const float keep = (lane & off) ? vj : A[i];
                A[i] = keep + recv;
            }
        }

        // ---- bias + relu + store ----
        if (lane < 16) {
            const float v = fmaxf(A[0] + bias, 0.f);
            if (cs < 2) {
                if (it < TSTEPS) *pW = v;
            } else {
                if (it >= 1) *pW = v;
            }
        }

        if (it == TSTEPS) break;

        __syncthreads();                       // all CTA stores issued
        if (tid == 0) red_release_add1(cnt);   // arrive (release)

        // ---- wait window: zero accs, fold x-dot for it+1, advance pointers ----
#pragma unroll
        for (int i = 0; i < 16; ++i) A[i] = 0.f;
        if (cs < 2 && it + 1 < TSTEPS) {
#pragma unroll
            for (int i = 0; i < 2; ++i) {
                float4 w[4];
#pragma unroll
                for (int c = 0; c < 4; ++c) w[c] = *(const float4*)&Wx[c * KDIM + 4 * lane + 128 * i];
#pragma unroll
                for (int b = 0; b < 4; ++b) {
                    const float4 a = *(const float4*)&pX[b * XSTRIDE_B + 128 * i];
#pragma unroll
                    for (int c = 0; c < 4; ++c)
                        A[b * 4 + c] += a.x * w[c].x + a.y * w[c].y
                                      + a.z * w[c].z + a.w * w[c].w;
                }
            }
        }
        pX  += IN_DIM;
        pHr += HID_DIM;
        pRr += OUT_DIM;
        pW  += (cs < 2) ? HID_DIM : OUT_DIM;

        // ---- wait for this half's epoch: t0 polls L2, relays via smem flag ----
        const int epoch = it + 1;
        if (tid == 0) {
            const unsigned tgt = 64u * (unsigned)epoch;
            while ((int)(ld_acquire_u32(cnt) - tgt) < 0) {}
            bar_flag = epoch;
        } else if (lane == 0) {
            while (bar_flag < epoch) {}
        }
        __syncwarp();
    }

    // ---- reset epoch counters for the next graph replay ----
    grid_barrier();
    if (cta < 2 && tid == 0) g_cnt[cta * 64] = 0;
}

extern "C" void kernel_launch(void* const* d_in, const int* in_sizes, int n_in,
                              void* d_out, int out_size) {
    const float* X   = (const float*)d_in[0];
    const float* H0  = (const float*)d_in[1];
    const float* R0  = (const float*)d_in[2];
    const float* Wih = (const float*)d_in[3];
    const float* Bih = (const float*)d_in[4];
    const float* Who = (const float*)d_in[5];
    const float* Bho = (const float*)d_in[6];

    float* Rout = (float*)d_out;                                   // [64][1025][256]
    float* Hout = (float*)d_out + (size_t)BATCH * 1025 * OUT_DIM;  // [64][1025][512]

    rnn_persistent_kernel<<<NCTA, NTHR>>>(X, H0, R0, Wih, Bih, Who, Bho, Rout, Hout);
}